// round 16
// baseline (speedup 1.0000x reference)
#include <cuda_runtime.h>
#include <cstdint>

// out[i, :] = table[idx[i], :]
// table: [2,000,000 x 128] f32.  idx: [1,048,576] int32 (JAX silently downcasts
// jnp.int64 when x64 is off) — confirmed by R10 pass — but a cheap runtime
// probe keeps int64 working too.
//
// R10 measured: 160.6us total, gather kernel 155.1us, DRAM 81.4%, HBM 6450GB/s.
// R11 changes (pending measurement):
//   1. Parallel dtype probe (32 lanes, ballot) — one memory round trip instead
//      of a serial 64-iteration loop: cuts ~3-4us of overhead.
//   2. ROWS_PER_WARP 4 -> 8: 8 front-batched independent 512B gathers per warp
//      doubles per-warp MLP to help fill HBM across read/write turnarounds
//      (DRAM was 81.4%, target ~85%+). ~40-48 regs, occupancy still ample for
//      a bandwidth-bound kernel (issue was only 18.8%).
// Reads stay 4 contiguous 128B lines per row (coalesced); writes stream to 8
// adjacent rows with st.global.cs (evict-first) so the write-once output does
// not thrash L2 lines the randomly-gathered table wants.

static constexpr long long NUM_NODES = 2000000;
static constexpr int EMB_DIM = 128;
static constexpr int VEC_PER_ROW = EMB_DIM / 4;   // 32 float4 lanes per row
static constexpr int ROWS_PER_WARP = 8;

__device__ int g_idx_is_i64;   // 1 = indices are int64, 0 = int32

// Parallel probe: 32 lanes x 2 values = first 64 values viewed as int64.
// Real int64 indices all lie in [0, NUM_NODES). Int32 data misread as int64
// packs two indices per value (lo + hi*2^32); for uniform random indices the
// chance all 64 probed values have hi==0 is ~0, so any out-of-range value
// => int32. Reads 512 B, safe for either layout (idx buffer >= 4 MiB).
__global__ void detect_idx_dtype_kernel(const long long* __restrict__ idx64)
{
    const int lane = threadIdx.x & 31;
    const long long v0 = idx64[lane];
    const long long v1 = idx64[lane + 32];
    const bool ok = (v0 >= 0 && v0 < NUM_NODES) && (v1 >= 0 && v1 < NUM_NODES);
    const unsigned all_ok = __all_sync(0xFFFFFFFFu, ok);
    if (lane == 0) g_idx_is_i64 = all_ok ? 1 : 0;
}

__device__ __forceinline__ long long load_row_index(const void* idx_raw,
                                                    int i, int is64)
{
    long long row = is64 ? __ldg(((const long long*)idx_raw) + i)
                         : (long long)__ldg(((const int*)idx_raw) + i);
    // Clamp: a wrong dtype theory becomes rel_err, not an illegal access.
    if (row < 0) row = 0;
    if (row >= NUM_NODES) row = NUM_NODES - 1;
    return row;
}

__global__ __launch_bounds__(256)
void gather_rows_kernel(const float4* __restrict__ table,
                        const void* __restrict__ idx_raw,
                        float4* __restrict__ out,
                        int num_ids)
{
    const int warp_id = (blockIdx.x * blockDim.x + threadIdx.x) >> 5;
    const int lane    = threadIdx.x & 31;
    const int i0      = warp_id * ROWS_PER_WARP;
    if (i0 >= num_ids) return;

    const int is64 = g_idx_is_i64;

    // Front-batch all index loads (warp-uniform broadcasts).
    long long r[ROWS_PER_WARP];
    #pragma unroll
    for (int k = 0; k < ROWS_PER_WARP; ++k) {
        const int i = i0 + k;
        r[k] = (i < num_ids) ? load_row_index(idx_raw, i, is64) : 0;
    }

    // Front-batch all row gathers: 8 independent 512 B loads in flight.
    float4 v[ROWS_PER_WARP];
    #pragma unroll
    for (int k = 0; k < ROWS_PER_WARP; ++k)
        v[k] = __ldg(&table[r[k] * (long long)VEC_PER_ROW + lane]);

    // Streaming (evict-first) stores to 8 adjacent output rows.
    float4* o = out + (long long)i0 * VEC_PER_ROW + lane;
    #pragma unroll
    for (int k = 0; k < ROWS_PER_WARP; ++k)
        if (i0 + k < num_ids) __stcs(&o[(long long)k * VEC_PER_ROW], v[k]);
}

extern "C" void kernel_launch(void* const* d_in, const int* in_sizes, int n_in,
                              void* d_out, int out_size)
{
    const float4* table = (const float4*)d_in[0];
    const void*   idx   = d_in[1];
    float4*       out   = (float4*)d_out;

    const int num_ids = in_sizes[1];          // 1,048,576

    detect_idx_dtype_kernel<<<1, 32>>>((const long long*)idx);

    const int threads = 256;                                   // 8 warps/block
    const int rows_per_block = (threads / 32) * ROWS_PER_WARP; // 64 rows
    const int blocks = (num_ids + rows_per_block - 1) / rows_per_block;
    gather_rows_kernel<<<blocks, threads>>>(table, idx, out, num_ids);
}